// round 6
// baseline (speedup 1.0000x reference)
#include <cuda_runtime.h>

#define EMBED 1024
#define NHEAD 16
#define HDIM  64
#define BB    2
#define NSEQ  2048

// ---- device scratch (static: allocation rules forbid cudaMalloc) ----
__device__ float g_Q[BB*NHEAD*NSEQ*HDIM];     // 16 MB
__device__ float g_K[BB*NHEAD*NSEQ*HDIM];     // 16 MB
__device__ float g_V[BB*NHEAD*NSEQ*HDIM];     // 16 MB
__device__ float g_attn[BB*NSEQ*EMBED];       // 16 MB  [B,N,C] with C = h*64+d

// ============================================================
// Kernel 1: QKV GEMM  [4096,1024] @ [1024,3072] + bias
// 128x128x16 tiles, 256 threads, 8x8 microtile.
// Epilogue scatters into g_Q/g_K/g_V in [B,H,N,D] layout.
// ============================================================
__global__ __launch_bounds__(256) void qkv_gemm_kernel(
    const float* __restrict__ X, const float* __restrict__ W,
    const float* __restrict__ bias)
{
    const int K = EMBED;       // 1024
    const int N = 3 * EMBED;   // 3072
    __shared__ float As[16][132];   // A^T tile (k-major), padded
    __shared__ float Bs[16][128];

    int tid = threadIdx.x;
    int bm = blockIdx.y * 128;
    int bn = blockIdx.x * 128;
    int ty = tid >> 4, tx = tid & 15;

    float acc[8][8];
#pragma unroll
    for (int i = 0; i < 8; i++)
#pragma unroll
        for (int j = 0; j < 8; j++) acc[i][j] = 0.f;

    for (int k0 = 0; k0 < K; k0 += 16) {
#pragma unroll
        for (int s = 0; s < 2; s++) {
            int lin = tid + s * 256;             // 0..511 float4 slots
            int m  = lin >> 2;
            int k4 = (lin & 3) << 2;
            float4 v = *(const float4*)(X + (size_t)(bm + m) * K + k0 + k4);
            As[k4 + 0][m] = v.x; As[k4 + 1][m] = v.y;
            As[k4 + 2][m] = v.z; As[k4 + 3][m] = v.w;
            int kk = lin >> 5;
            int n4 = (lin & 31) << 2;
            *(float4*)&Bs[kk][n4] =
                *(const float4*)(W + (size_t)(k0 + kk) * N + bn + n4);
        }
        __syncthreads();
#pragma unroll
        for (int kk = 0; kk < 16; kk++) {
            float a[8], b[8];
#pragma unroll
            for (int i = 0; i < 8; i++) a[i] = As[kk][ty * 8 + i];
#pragma unroll
            for (int j = 0; j < 8; j++) b[j] = Bs[kk][tx * 8 + j];
#pragma unroll
            for (int i = 0; i < 8; i++)
#pragma unroll
                for (int j = 0; j < 8; j++)
                    acc[i][j] = fmaf(a[i], b[j], acc[i][j]);
        }
        __syncthreads();
    }

    // epilogue: add bias, scatter into Q/K/V [B,H,N,D]
#pragma unroll
    for (int i = 0; i < 8; i++) {
        int row = bm + ty * 8 + i;       // 0..4095
        int b = row >> 11;               // /2048
        int n = row & 2047;
#pragma unroll
        for (int j = 0; j < 8; j++) {
            int col = bn + tx * 8 + j;   // 0..3071
            float v = acc[i][j] + bias[col];
            int t = col >> 10;
            int h = (col >> 6) & 15;
            int d = col & 63;
            size_t idx = ((size_t)(b * NHEAD + h) * NSEQ + n) * HDIM + d;
            if (t == 0)      g_Q[idx] = v;
            else if (t == 1) g_K[idx] = v;
            else             g_V[idx] = v;
        }
    }
}

// ============================================================
// Kernel 2: flash attention per (b,h). BM=32 queries, BN=64 keys.
// 128 threads: ty=tid/16 (row group of 4), tx=tid%16 (4 cols/dims).
// Online softmax; P tile reuses the K smem buffer.
// ============================================================
__global__ __launch_bounds__(128) void flash_kernel()
{
    __shared__ float Qs[32][65];
    __shared__ float KPs[64][65];   // K tile; reused as P[32][64]
    __shared__ float Vs[64][64];

    int tid = threadIdx.x;
    int bh  = blockIdx.y;                   // 0..31 = b*16+h
    int q0  = blockIdx.x * 32;
    size_t base = (size_t)bh * NSEQ * HDIM;
    int ty = tid >> 4;      // 0..7
    int tx = tid & 15;      // 0..15

    const float scale = 0.125f;   // 64^-0.5

    // load Q tile, pre-scaled
#pragma unroll
    for (int s = 0; s < 16; s++) {
        int lin = tid + s * 128;            // 0..2047
        int r = lin >> 6, d = lin & 63;
        Qs[r][d] = g_Q[base + (size_t)(q0 + r) * HDIM + d] * scale;
    }

    float m_i[4], l_i[4], acc[4][4];
#pragma unroll
    for (int i = 0; i < 4; i++) {
        m_i[i] = -1e30f; l_i[i] = 0.f;
#pragma unroll
        for (int j = 0; j < 4; j++) acc[i][j] = 0.f;
    }

    for (int kt = 0; kt < NSEQ; kt += 64) {
        __syncthreads();   // prior iter done reading KPs(P)/Vs; Q visible
#pragma unroll
        for (int s = 0; s < 32; s++) {
            int lin = tid + s * 128;        // 0..4095
            int c = lin >> 6, d = lin & 63;
            KPs[c][d] = g_K[base + (size_t)(kt + c) * HDIM + d];
            Vs[c][d]  = g_V[base + (size_t)(kt + c) * HDIM + d];
        }
        __syncthreads();

        // S = Q K^T (scaled)
        float s4[4][4];
#pragma unroll
        for (int i = 0; i < 4; i++)
#pragma unroll
            for (int j = 0; j < 4; j++) s4[i][j] = 0.f;
        for (int d = 0; d < 64; d++) {
            float qa[4], kb[4];
#pragma unroll
            for (int i = 0; i < 4; i++) qa[i] = Qs[ty * 4 + i][d];
#pragma unroll
            for (int j = 0; j < 4; j++) kb[j] = KPs[tx * 4 + j][d];
#pragma unroll
            for (int i = 0; i < 4; i++)
#pragma unroll
                for (int j = 0; j < 4; j++)
                    s4[i][j] = fmaf(qa[i], kb[j], s4[i][j]);
        }

        // per-row max across the 16-lane tx group
        float mt[4];
#pragma unroll
        for (int i = 0; i < 4; i++) {
            mt[i] = s4[i][0];
#pragma unroll
            for (int j = 1; j < 4; j++) mt[i] = fmaxf(mt[i], s4[i][j]);
        }
#pragma unroll
        for (int off = 8; off >= 1; off >>= 1)
#pragma unroll
            for (int i = 0; i < 4; i++)
                mt[i] = fmaxf(mt[i], __shfl_xor_sync(0xffffffffu, mt[i], off));

        float p[4][4], ps[4], alpha[4];
#pragma unroll
        for (int i = 0; i < 4; i++) {
            float mnew = fmaxf(m_i[i], mt[i]);
            alpha[i] = __expf(m_i[i] - mnew);
            m_i[i] = mnew;
            ps[i] = 0.f;
#pragma unroll
            for (int j = 0; j < 4; j++) {
                p[i][j] = __expf(s4[i][j] - mnew);
                ps[i] += p[i][j];
            }
        }
#pragma unroll
        for (int off = 8; off >= 1; off >>= 1)
#pragma unroll
            for (int i = 0; i < 4; i++)
                ps[i] += __shfl_xor_sync(0xffffffffu, ps[i], off);
#pragma unroll
        for (int i = 0; i < 4; i++) {
            l_i[i] = l_i[i] * alpha[i] + ps[i];
#pragma unroll
            for (int j = 0; j < 4; j++) acc[i][j] *= alpha[i];
        }

        __syncthreads();   // everyone done reading K tile
#pragma unroll
        for (int i = 0; i < 4; i++)
#pragma unroll
            for (int j = 0; j < 4; j++)
                KPs[ty * 4 + i][tx * 4 + j] = p[i][j];   // P[r][c]
        __syncthreads();

        // O += P @ V  (thread dims dd = tx*4..tx*4+3)
#pragma unroll 8
        for (int c = 0; c < 64; c++) {
            float pv[4];
#pragma unroll
            for (int i = 0; i < 4; i++) pv[i] = KPs[ty * 4 + i][c];
            float4 vv = *(const float4*)&Vs[c][tx * 4];
#pragma unroll
            for (int i = 0; i < 4; i++) {
                acc[i][0] = fmaf(pv[i], vv.x, acc[i][0]);
                acc[i][1] = fmaf(pv[i], vv.y, acc[i][1]);
                acc[i][2] = fmaf(pv[i], vv.z, acc[i][2]);
                acc[i][3] = fmaf(pv[i], vv.w, acc[i][3]);
            }
        }
    }

    // epilogue: normalize, write [B,N,C] with C = h*64 + d
    int b = bh >> 4, h = bh & 15;
#pragma unroll
    for (int i = 0; i < 4; i++) {
        int n = q0 + ty * 4 + i;
        float inv = 1.f / l_i[i];
        float4 o;
        o.x = acc[i][0] * inv; o.y = acc[i][1] * inv;
        o.z = acc[i][2] * inv; o.w = acc[i][3] * inv;
        *(float4*)&g_attn[((size_t)(b * NSEQ + n)) * EMBED + h * 64 + tx * 4] = o;
    }
}

// ============================================================
// Kernel 3: output projection  [4096,1024] @ [1024,1024] + bias
// Same SGEMM structure, plain epilogue to d_out.
// ============================================================
__global__ __launch_bounds__(256) void proj_gemm_kernel(
    const float* __restrict__ W, const float* __restrict__ bias,
    float* __restrict__ Out)
{
    const int K = EMBED;       // 1024
    const int N = EMBED;       // 1024
    __shared__ float As[16][132];
    __shared__ float Bs[16][128];

    int tid = threadIdx.x;
    int bm = blockIdx.y * 128;
    int bn = blockIdx.x * 128;
    int ty = tid >> 4, tx = tid & 15;

    float acc[8][8];
#pragma unroll
    for (int i = 0; i < 8; i++)
#pragma unroll
        for (int j = 0; j < 8; j++) acc[i][j] = 0.f;

    for (int k0 = 0; k0 < K; k0 += 16) {
#pragma unroll
        for (int s = 0; s < 2; s++) {
            int lin = tid + s * 256;
            int m  = lin >> 2;
            int k4 = (lin & 3) << 2;
            float4 v = *(const float4*)(g_attn + (size_t)(bm + m) * K + k0 + k4);
            As[k4 + 0][m] = v.x; As[k4 + 1][m] = v.y;
            As[k4 + 2][m] = v.z; As[k4 + 3][m] = v.w;
            int kk = lin >> 5;
            int n4 = (lin & 31) << 2;
            *(float4*)&Bs[kk][n4] =
                *(const float4*)(W + (size_t)(k0 + kk) * N + bn + n4);
        }
        __syncthreads();
#pragma unroll
        for (int kk = 0; kk < 16; kk++) {
            float a[8], b[8];
#pragma unroll
            for (int i = 0; i < 8; i++) a[i] = As[kk][ty * 8 + i];
#pragma unroll
            for (int j = 0; j < 8; j++) b[j] = Bs[kk][tx * 8 + j];
#pragma unroll
            for (int i = 0; i < 8; i++)
#pragma unroll
                for (int j = 0; j < 8; j++)
                    acc[i][j] = fmaf(a[i], b[j], acc[i][j]);
        }
        __syncthreads();
    }

#pragma unroll
    for (int i = 0; i < 8; i++) {
        int row = bm + ty * 8 + i;
#pragma unroll
        for (int j4 = 0; j4 < 2; j4++) {
            int col = bn + tx * 8 + j4 * 4;
            float4 bb = *(const float4*)&bias[col];
            float4 o;
            o.x = acc[i][j4 * 4 + 0] + bb.x;
            o.y = acc[i][j4 * 4 + 1] + bb.y;
            o.z = acc[i][j4 * 4 + 2] + bb.z;
            o.w = acc[i][j4 * 4 + 3] + bb.w;
            *(float4*)&Out[(size_t)row * N + col] = o;
        }
    }
}

// ============================================================
extern "C" void kernel_launch(void* const* d_in, const int* in_sizes, int n_in,
                              void* d_out, int out_size)
{
    const float* x     = (const float*)d_in[0];  // [2,2048,1024]
    const float* W_qkv = (const float*)d_in[1];  // [1024,3072]
    const float* b_qkv = (const float*)d_in[2];  // [3072]
    const float* W_p   = (const float*)d_in[3];  // [1024,1024]
    const float* b_p   = (const float*)d_in[4];  // [1024]
    float* out = (float*)d_out;                  // [2,2048,1024]

    qkv_gemm_kernel<<<dim3(24, 32), 256>>>(x, W_qkv, b_qkv);
    flash_kernel<<<dim3(64, 32), 128>>>();
    proj_gemm_kernel<<<dim3(8, 32), 256>>>(W_p, b_p, out);
}